// round 7
// baseline (speedup 1.0000x reference)
#include <cuda_runtime.h>
#include <cuda_fp16.h>
#include <cstdint>

#define NN 50000
#define NE 800000
#define NB 98        // scan blocks: 98*512 >= 50000
#define HA 25088     // first-half nodes (multiple of 128 and 64)
#define HB (NN - HA) // 24912 (multiple of 8)

// ---------------------------------------------------------------------------
// Scratch (static device arrays: allocation-free per harness rules)
// ---------------------------------------------------------------------------
__device__ __half g_tmpA[NN * 128];
__device__ __half g_tmpB[NN * 128];
__device__ float  g_h[NN * 128];
__device__ float  g_dinv[NN];
__device__ int    g_deg[NN];
__device__ int    g_rowptr[NN + 1];
__device__ int    g_cursor[NN];
__device__ int    g_csr[NE];
__device__ int    g_bsum[NB];

// ---------------------------------------------------------------------------
// Host-side stream/event context (host resources only; created at static init)
// ---------------------------------------------------------------------------
struct Ctx {
    cudaStream_t s;
    cudaEvent_t e[12];
    Ctx() {
        cudaStreamCreateWithFlags(&s, cudaStreamNonBlocking);
        for (int i = 0; i < 12; i++) cudaEventCreateWithFlags(&e[i], cudaEventDisableTiming);
    }
};
static Ctx g_ctx;

// ---------------------------------------------------------------------------
// degree / normalization
// ---------------------------------------------------------------------------
__global__ void k_deg_init(int* __restrict__ deg) {
    int i = blockIdx.x * blockDim.x + threadIdx.x;
    if (i < NN) deg[i] = 1;  // self-loop
}
__global__ void k_deg_count(const int* __restrict__ ei, int* __restrict__ deg) {
    int e = blockIdx.x * blockDim.x + threadIdx.x;
    if (e < NE) atomicAdd(&deg[ei[NE + e]], 1);
}
__global__ void k_dinv(const int* __restrict__ deg, float* __restrict__ dinv) {
    int i = blockIdx.x * blockDim.x + threadIdx.x;
    if (i < NN) dinv[i] = rsqrtf((float)deg[i]);
}

// ---------------------------------------------------------------------------
// CSR build: exclusive scan of edge counts (deg-1), then cursor fill.
// ---------------------------------------------------------------------------
__global__ void k_scan1(const int* __restrict__ deg, int* __restrict__ rowptr,
                        int* __restrict__ bsum) {
    __shared__ int s[512];
    int tid = threadIdx.x;
    int i = blockIdx.x * 512 + tid;
    int v = (i < NN) ? (deg[i] - 1) : 0;
    s[tid] = v;
    __syncthreads();
    for (int o = 1; o < 512; o <<= 1) {
        int t = (tid >= o) ? s[tid - o] : 0;
        __syncthreads();
        s[tid] += t;
        __syncthreads();
    }
    if (i < NN) rowptr[i] = s[tid] - v;
    if (tid == 511) bsum[blockIdx.x] = s[511];
}
__global__ void k_scan2(int* __restrict__ bsum) {
    if (threadIdx.x == 0 && blockIdx.x == 0) {
        int acc = 0;
        for (int i = 0; i < NB; i++) { int v = bsum[i]; bsum[i] = acc; acc += v; }
    }
}
__global__ void k_scan3(int* __restrict__ rowptr, const int* __restrict__ bsum,
                        int* __restrict__ cursor) {
    int i = blockIdx.x * 512 + threadIdx.x;
    if (i < NN) {
        int r = rowptr[i] + bsum[blockIdx.x];
        rowptr[i] = r;
        cursor[i] = r;
    }
    if (blockIdx.x == 0 && threadIdx.x == 0) rowptr[NN] = NE;
}
__global__ void k_fill(const int* __restrict__ ei, int* __restrict__ cursor,
                       int* __restrict__ csr) {
    int e = blockIdx.x * blockDim.x + threadIdx.x;
    if (e >= NE) return;
    int dst = ei[NE + e];
    int pos = atomicAdd(&cursor[dst], 1);
    csr[pos] = ei[e];
}

// ---------------------------------------------------------------------------
// GEMM 128x128: out[row] = fp16( (A[row] @ W) [* scale[row]] )
// 512 threads, thread tile 8 rows x 4 cols, FFMA2 (fma.rn.f32x2) inner loop.
// ---------------------------------------------------------------------------
#define FFMA2(d, a, b) asm("fma.rn.f32x2 %0, %1, %2, %0;" : "+l"(d) : "l"(a), "l"(b))
#define PACK2(d, a)    asm("mov.b64 %0, {%1, %1};" : "=l"(d) : "f"(a))
union U64F2 { unsigned long long u; float2 f; };

static constexpr int GM_WS  = 0;
static constexpr int GM_AT  = 128 * 128;
static constexpr int GM_STG = 2 * 128 * 128;
static constexpr int GM_SMEM_FLOATS = 2 * 128 * 128 + 128 * 129;
static constexpr int GM_SMEM_BYTES  = GM_SMEM_FLOATS * 4;   // 197120

__global__ void __launch_bounds__(512, 1)
k_gemm128(const float* __restrict__ A, const float* __restrict__ W,
          const float* __restrict__ scale, __half* __restrict__ out, int nrows) {
    extern __shared__ float sm[];
    float* Ws  = sm + GM_WS;
    float* At  = sm + GM_AT;
    float* Stg = sm + GM_STG;

    const int tid  = threadIdx.x;
    const int row0 = blockIdx.x * 128;

    {
        const float4* w4 = (const float4*)W;
        float4* s4 = (float4*)Ws;
        for (int i = tid; i < 4096; i += 512) s4[i] = w4[i];
    }
    for (int i = tid; i < 4096; i += 512) {
        int r = i >> 5, kq = i & 31;
        int grow = row0 + r;
        float4 f = make_float4(0.f, 0.f, 0.f, 0.f);
        if (grow < nrows) f = ((const float4*)A)[(size_t)grow * 32 + kq];
        float* p = Stg + r * 129 + kq * 4;
        p[0] = f.x; p[1] = f.y; p[2] = f.z; p[3] = f.w;
    }
    __syncthreads();
    for (int i = tid; i < 16384; i += 512) {
        int r = i & 127, k = i >> 7;
        At[k * 128 + r] = Stg[r * 129 + k];
    }
    __syncthreads();

    const int tc = tid & 31;
    const int tr = tid >> 5;

    unsigned long long acc[8][2];
#pragma unroll
    for (int i = 0; i < 8; i++) { acc[i][0] = 0ull; acc[i][1] = 0ull; }

    const float* Wp = Ws + 4 * tc;
    const float* Ap = At + 8 * tr;

#pragma unroll 4
    for (int k = 0; k < 128; k++) {
        ulonglong2 wv = *(const ulonglong2*)(Wp + k * 128);
        float4 a0 = *(const float4*)(Ap + k * 128);
        float4 a1 = *(const float4*)(Ap + k * 128 + 4);
        unsigned long long p0, p1, p2, p3, p4, p5, p6, p7;
        PACK2(p0, a0.x); PACK2(p1, a0.y); PACK2(p2, a0.z); PACK2(p3, a0.w);
        PACK2(p4, a1.x); PACK2(p5, a1.y); PACK2(p6, a1.z); PACK2(p7, a1.w);
        FFMA2(acc[0][0], p0, wv.x); FFMA2(acc[0][1], p0, wv.y);
        FFMA2(acc[1][0], p1, wv.x); FFMA2(acc[1][1], p1, wv.y);
        FFMA2(acc[2][0], p2, wv.x); FFMA2(acc[2][1], p2, wv.y);
        FFMA2(acc[3][0], p3, wv.x); FFMA2(acc[3][1], p3, wv.y);
        FFMA2(acc[4][0], p4, wv.x); FFMA2(acc[4][1], p4, wv.y);
        FFMA2(acc[5][0], p5, wv.x); FFMA2(acc[5][1], p5, wv.y);
        FFMA2(acc[6][0], p6, wv.x); FFMA2(acc[6][1], p6, wv.y);
        FFMA2(acc[7][0], p7, wv.x); FFMA2(acc[7][1], p7, wv.y);
    }

#pragma unroll
    for (int i = 0; i < 8; i++) {
        int row = row0 + 8 * tr + i;
        if (row < nrows) {
            float s = scale ? scale[row] : 1.0f;
            U64F2 u0, u1;
            u0.u = acc[i][0];
            u1.u = acc[i][1];
            __half2 h0 = __floats2half2_rn(u0.f.x * s, u0.f.y * s);
            __half2 h1 = __floats2half2_rn(u1.f.x * s, u1.f.y * s);
            uint2 pk = make_uint2(*(uint32_t*)&h0, *(uint32_t*)&h1);
            ((uint2*)(out + (size_t)row * 128))[tc] = pk;
        }
    }
}

// ---------------------------------------------------------------------------
// Aggregate (CSR gather of fp16 rows) over node range [n0, n0+ncnt):
// One warp per node; lane owns 4 halves (8B). fp32 accumulation.
// 8-wide edge unroll: batch index loads then 8 independent row loads (MLP~16).
// ---------------------------------------------------------------------------
__device__ __forceinline__ float4 h4f4(uint2 r) {
    __half2 a = *(__half2*)&r.x, b = *(__half2*)&r.y;
    float2 fa = __half22float2(a), fb = __half22float2(b);
    return make_float4(fa.x, fa.y, fb.x, fb.y);
}
__device__ __forceinline__ void f4add(float4& d, float4 v) {
    d.x += v.x; d.y += v.y; d.z += v.z; d.w += v.w;
}
__device__ __forceinline__ void f4fma(float4& d, float4 v, float s) {
    d.x = fmaf(v.x, s, d.x); d.y = fmaf(v.y, s, d.y);
    d.z = fmaf(v.z, s, d.z); d.w = fmaf(v.w, s, d.w);
}

__global__ void k_agg(const int* __restrict__ rowptr, const int* __restrict__ csr,
                      const __half* __restrict__ tmp, const float* __restrict__ dinv,
                      const float* __restrict__ edinv, const float* __restrict__ bias,
                      float* __restrict__ out, int n0, int ncnt) {
    int wi = (blockIdx.x * blockDim.x + threadIdx.x) >> 5;
    if (wi >= ncnt) return;
    int w = n0 + wi;
    int lane = threadIdx.x & 31;
    const uint2* t2 = (const uint2*)tmp;   // 32 uint2 per 128-half row

    float4 self = h4f4(t2[(size_t)w * 32 + lane]);
    float se = edinv ? edinv[w] : 1.0f;
    float4 a0 = make_float4(self.x * se, self.y * se, self.z * se, self.w * se);
    float4 a1 = make_float4(0.f, 0.f, 0.f, 0.f);
    float4 a2 = make_float4(0.f, 0.f, 0.f, 0.f);
    float4 a3 = make_float4(0.f, 0.f, 0.f, 0.f);

    int e   = __ldg(rowptr + w);
    int end = __ldg(rowptr + w + 1);

    if (edinv) {
        // layer 1 path: per-source dinv scaling, 4-wide
        for (; e + 3 < end; e += 4) {
            int s0 = __ldg(csr + e + 0), s1 = __ldg(csr + e + 1);
            int s2 = __ldg(csr + e + 2), s3 = __ldg(csr + e + 3);
            float e0 = __ldg(edinv + s0), e1 = __ldg(edinv + s1);
            float e2 = __ldg(edinv + s2), e3 = __ldg(edinv + s3);
            uint2 r0 = t2[(size_t)s0 * 32 + lane];
            uint2 r1 = t2[(size_t)s1 * 32 + lane];
            uint2 r2 = t2[(size_t)s2 * 32 + lane];
            uint2 r3 = t2[(size_t)s3 * 32 + lane];
            f4fma(a0, h4f4(r0), e0);
            f4fma(a1, h4f4(r1), e1);
            f4fma(a2, h4f4(r2), e2);
            f4fma(a3, h4f4(r3), e3);
        }
        for (; e < end; e++) {
            int s0 = __ldg(csr + e);
            float e0 = __ldg(edinv + s0);
            f4fma(a0, h4f4(t2[(size_t)s0 * 32 + lane]), e0);
        }
    } else {
        // 8-wide: batch the (uniform) index loads, then 8 independent gathers
        for (; e + 7 < end; e += 8) {
            int s0 = __ldg(csr + e + 0), s1 = __ldg(csr + e + 1);
            int s2 = __ldg(csr + e + 2), s3 = __ldg(csr + e + 3);
            int s4 = __ldg(csr + e + 4), s5 = __ldg(csr + e + 5);
            int s6 = __ldg(csr + e + 6), s7 = __ldg(csr + e + 7);
            uint2 r0 = t2[(size_t)s0 * 32 + lane];
            uint2 r1 = t2[(size_t)s1 * 32 + lane];
            uint2 r2 = t2[(size_t)s2 * 32 + lane];
            uint2 r3 = t2[(size_t)s3 * 32 + lane];
            uint2 r4 = t2[(size_t)s4 * 32 + lane];
            uint2 r5 = t2[(size_t)s5 * 32 + lane];
            uint2 r6 = t2[(size_t)s6 * 32 + lane];
            uint2 r7 = t2[(size_t)s7 * 32 + lane];
            f4add(a0, h4f4(r0)); f4add(a1, h4f4(r1));
            f4add(a2, h4f4(r2)); f4add(a3, h4f4(r3));
            f4add(a0, h4f4(r4)); f4add(a1, h4f4(r5));
            f4add(a2, h4f4(r6)); f4add(a3, h4f4(r7));
        }
        for (; e + 1 < end; e += 2) {
            int s0 = __ldg(csr + e), s1 = __ldg(csr + e + 1);
            uint2 r0 = t2[(size_t)s0 * 32 + lane];
            uint2 r1 = t2[(size_t)s1 * 32 + lane];
            f4add(a0, h4f4(r0));
            f4add(a1, h4f4(r1));
        }
        if (e < end) {
            int s0 = __ldg(csr + e);
            f4add(a0, h4f4(t2[(size_t)s0 * 32 + lane]));
        }
    }
    a0.x += a1.x + a2.x + a3.x;
    a0.y += a1.y + a2.y + a3.y;
    a0.z += a1.z + a2.z + a3.z;
    a0.w += a1.w + a2.w + a3.w;

    float sc = dinv[w];
    float4 b = ((const float4*)bias)[lane];
    a0.x = fmaxf(fmaf(a0.x, sc, b.x), 0.0f);
    a0.y = fmaxf(fmaf(a0.y, sc, b.y), 0.0f);
    a0.z = fmaxf(fmaf(a0.z, sc, b.z), 0.0f);
    a0.w = fmaxf(fmaf(a0.w, sc, b.w), 0.0f);
    ((float4*)out)[(size_t)w * 32 + lane] = a0;
}

// ---------------------------------------------------------------------------
// Classifier SIMT GEMM (BN=40), FFMA2 path.
// ---------------------------------------------------------------------------
template <int BN>
__global__ void k_gemm_cls(const float* __restrict__ A, const float* __restrict__ W,
                           const float* __restrict__ bias,
                           float* __restrict__ out0, int nrows) {
    constexpr int BM = 64;
    constexpr int TX = BN / 4;
    constexpr int TY = BM / 4;
    constexpr int NT = TX * TY;

    extern __shared__ float fsm[];
    float*  Ws = fsm;
    float2* Ad = (float2*)(fsm + 128 * BN);
    float*  As = (float*)(Ad + 128 * BM);

    const int tid  = threadIdx.x;
    const int row0 = blockIdx.x * BM;

    for (int idx = tid; idx < 128 * BN; idx += NT) Ws[idx] = W[idx];
    for (int idx = tid; idx < BM * 128; idx += NT) {
        int r = idx >> 7, k = idx & 127;
        int gr = row0 + r;
        As[r * 129 + k] = (gr < nrows) ? A[(size_t)gr * 128 + k] : 0.0f;
    }
    __syncthreads();
    for (int idx = tid; idx < 128 * BM; idx += NT) {
        int r = idx % BM, k = idx / BM;
        float v = As[r * 129 + k];
        Ad[idx] = make_float2(v, v);
    }
    __syncthreads();

    const int tc = tid % TX, tr = tid / TX;
    unsigned long long acc[4][2];
#pragma unroll
    for (int r = 0; r < 4; r++) { acc[r][0] = 0ull; acc[r][1] = 0ull; }

    const float2* adp = Ad + 4 * tr;
    const float*  wsp = Ws + 4 * tc;

#pragma unroll 8
    for (int k = 0; k < 128; k++) {
        ulonglong2 av0 = *(const ulonglong2*)(adp + (size_t)k * BM);
        ulonglong2 av1 = *(const ulonglong2*)(adp + (size_t)k * BM + 2);
        ulonglong2 wv  = *(const ulonglong2*)(wsp + (size_t)k * BN);
        FFMA2(acc[0][0], av0.x, wv.x); FFMA2(acc[0][1], av0.x, wv.y);
        FFMA2(acc[1][0], av0.y, wv.x); FFMA2(acc[1][1], av0.y, wv.y);
        FFMA2(acc[2][0], av1.x, wv.x); FFMA2(acc[2][1], av1.x, wv.y);
        FFMA2(acc[3][0], av1.y, wv.x); FFMA2(acc[3][1], av1.y, wv.y);
    }

#pragma unroll
    for (int r = 0; r < 4; r++) {
        int row = row0 + 4 * tr + r;
        if (row >= nrows) break;
        U64F2 u0, u1;
        u0.u = acc[r][0];
        u1.u = acc[r][1];
        float4 v = make_float4(u0.f.x + bias[4 * tc + 0], u0.f.y + bias[4 * tc + 1],
                               u1.f.x + bias[4 * tc + 2], u1.f.y + bias[4 * tc + 3]);
        *(float4*)(out0 + (size_t)row * BN + 4 * tc) = v;
    }
}

// ---------------------------------------------------------------------------
extern "C" void kernel_launch(void* const* d_in, const int* in_sizes, int n_in,
                              void* d_out, int out_size) {
    const float* x  = (const float*)d_in[0];
    const int*   ei = (const int*)d_in[1];
    const float* W1 = (const float*)d_in[2];
    const float* b1 = (const float*)d_in[3];
    const float* W2 = (const float*)d_in[4];
    const float* b2 = (const float*)d_in[5];
    const float* W3 = (const float*)d_in[6];
    const float* b3 = (const float*)d_in[7];
    const float* Wc = (const float*)d_in[8];
    const float* bc = (const float*)d_in[9];

    float* out_logits = (float*)d_out;                    // [NN,40]
    float* out_h      = (float*)d_out + (size_t)NN * 40;  // [NN,128]

    __half *tmpA, *tmpB;
    float *h, *dinv;
    int *deg, *rowptr, *cursor, *csr, *bsum;
    cudaGetSymbolAddress((void**)&tmpA,   g_tmpA);
    cudaGetSymbolAddress((void**)&tmpB,   g_tmpB);
    cudaGetSymbolAddress((void**)&h,      g_h);
    cudaGetSymbolAddress((void**)&dinv,   g_dinv);
    cudaGetSymbolAddress((void**)&deg,    g_deg);
    cudaGetSymbolAddress((void**)&rowptr, g_rowptr);
    cudaGetSymbolAddress((void**)&cursor, g_cursor);
    cudaGetSymbolAddress((void**)&csr,    g_csr);
    cudaGetSymbolAddress((void**)&bsum,   g_bsum);

    const int SM40 = 128 * 40 * 4 + 128 * 64 * 8 + 64 * 129 * 4;
    cudaFuncSetAttribute(k_gemm128, cudaFuncAttributeMaxDynamicSharedMemorySize, GM_SMEM_BYTES);
    cudaFuncSetAttribute(k_gemm_cls<40>, cudaFuncAttributeMaxDynamicSharedMemorySize, SM40);

    cudaStream_t S = g_ctx.s;
    cudaEvent_t* E = g_ctx.e;

    // fork side stream off the capture (main) stream
    cudaEventRecord(E[0], 0);
    cudaStreamWaitEvent(S, E[0], 0);

    // ---- side stream: normalization + CSR build (hidden behind GEMM1) ----
    k_deg_init<<<(NN + 255) / 256, 256, 0, S>>>(deg);
    k_deg_count<<<(NE + 255) / 256, 256, 0, S>>>(ei, deg);
    k_dinv<<<(NN + 255) / 256, 256, 0, S>>>(deg, dinv);
    k_scan1<<<NB, 512, 0, S>>>(deg, rowptr, bsum);
    k_scan2<<<1, 32, 0, S>>>(bsum);
    k_scan3<<<NB, 512, 0, S>>>(rowptr, bsum, cursor);
    k_fill<<<(NE + 255) / 256, 256, 0, S>>>(ei, cursor, csr);
    cudaEventRecord(E[1], S);   // CSR + dinv ready

    // ---- main: layer 1 GEMM -> tmpA (unscaled; no dinv dependency) ----
    k_gemm128<<<(NN + 127) / 128, 512, GM_SMEM_BYTES>>>(x, W1, nullptr, tmpA, NN);

    // agg layer 1 reads tmpA (dinv[src] per edge), writes h
    cudaStreamWaitEvent(0, E[1], 0);
    k_agg<<<HA / 8, 256>>>(rowptr, csr, tmpA, dinv, dinv, b1, h, 0, HA);
    cudaEventRecord(E[2], 0);   // h rows [0,HA) ready
    k_agg<<<HB / 8, 256>>>(rowptr, csr, tmpA, dinv, dinv, b1, h, HA, HB);

    // side: GEMM2-A (reads h[0:HA), writes tmpB) overlaps agg1-B (reads tmpA)
    cudaStreamWaitEvent(S, E[2], 0);
    k_gemm128<<<HA / 128, 512, GM_SMEM_BYTES, S>>>(h, W2, dinv, tmpB, HA);
    cudaEventRecord(E[3], S);
    // main: GEMM2-B
    k_gemm128<<<(HB + 127) / 128, 512, GM_SMEM_BYTES>>>(h + (size_t)HA * 128, W2,
                                                        dinv + HA, tmpB + (size_t)HA * 128, HB);
    cudaStreamWaitEvent(0, E[3], 0);
    // agg layer 2 reads tmpB, writes h
    k_agg<<<HA / 8, 256>>>(rowptr, csr, tmpB, dinv, nullptr, b2, h, 0, HA);
    cudaEventRecord(E[4], 0);
    k_agg<<<HB / 8, 256>>>(rowptr, csr, tmpB, dinv, nullptr, b2, h, HA, HB);

    // side: GEMM3-A (reads h[0:HA), writes tmpA) overlaps agg2-B (reads tmpB)
    cudaStreamWaitEvent(S, E[4], 0);
    k_gemm128<<<HA / 128, 512, GM_SMEM_BYTES, S>>>(h, W3, dinv, tmpA, HA);
    cudaEventRecord(E[5], S);
    // main: GEMM3-B
    k_gemm128<<<(HB + 127) / 128, 512, GM_SMEM_BYTES>>>(h + (size_t)HA * 128, W3,
                                                        dinv + HA, tmpA + (size_t)HA * 128, HB);
    cudaStreamWaitEvent(0, E[5], 0);
    // agg layer 3 reads tmpA, writes out_h
    k_agg<<<HA / 8, 256>>>(rowptr, csr, tmpA, dinv, nullptr, b3, out_h, 0, HA);
    cudaEventRecord(E[6], 0);
    k_agg<<<HB / 8, 256>>>(rowptr, csr, tmpA, dinv, nullptr, b3, out_h, HA, HB);

    // side: classifier-A (reads out_h[0:HA)) overlaps agg3-B (writes out_h[HA:))
    cudaStreamWaitEvent(S, E[6], 0);
    k_gemm_cls<40><<<HA / 64, 160, SM40, S>>>(out_h, Wc, bc, out_logits, HA);
    cudaEventRecord(E[7], S);
    // main: classifier-B
    k_gemm_cls<40><<<(HB + 63) / 64, 160, SM40>>>(out_h + (size_t)HA * 128, Wc, bc,
                                                  out_logits + (size_t)HA * 40, HB);
    // join side stream back into main before capture ends
    cudaStreamWaitEvent(0, E[7], 0);
}

// round 8
// speedup vs baseline: 1.0746x; 1.0746x over previous
#include <cuda_runtime.h>
#include <cuda_fp16.h>
#include <cstdint>

#define NN 50000
#define NE 800000
#define NB 98        // scan blocks: 98*512 >= 50000
#define HA 25088     // first-half nodes (multiple of 128, 64, 16)
#define HB (NN - HA) // 24912 (multiple of 16)

// ---------------------------------------------------------------------------
// Scratch (static device arrays: allocation-free per harness rules)
// ---------------------------------------------------------------------------
__device__ __half g_tmpA[NN * 128];
__device__ __half g_tmpB[NN * 128];
__device__ float  g_h[NN * 128];
__device__ float  g_dinv[NN];
__device__ int    g_deg[NN];
__device__ int    g_rowptr[NN + 1];
__device__ int    g_cursor[NN];
__device__ int    g_csr[NE];
__device__ int    g_bsum[NB];

// ---------------------------------------------------------------------------
// Host-side stream/event context (host resources only; created at static init)
// ---------------------------------------------------------------------------
struct Ctx {
    cudaStream_t s;
    cudaEvent_t e[12];
    Ctx() {
        cudaStreamCreateWithFlags(&s, cudaStreamNonBlocking);
        for (int i = 0; i < 12; i++) cudaEventCreateWithFlags(&e[i], cudaEventDisableTiming);
    }
};
static Ctx g_ctx;

// ---------------------------------------------------------------------------
// degree / normalization
// ---------------------------------------------------------------------------
__global__ void k_deg_init(int* __restrict__ deg) {
    int i = blockIdx.x * blockDim.x + threadIdx.x;
    if (i < NN) deg[i] = 1;  // self-loop
}
__global__ void k_deg_count(const int* __restrict__ ei, int* __restrict__ deg) {
    int e = blockIdx.x * blockDim.x + threadIdx.x;
    if (e < NE) atomicAdd(&deg[ei[NE + e]], 1);
}
__global__ void k_dinv(const int* __restrict__ deg, float* __restrict__ dinv) {
    int i = blockIdx.x * blockDim.x + threadIdx.x;
    if (i < NN) dinv[i] = rsqrtf((float)deg[i]);
}

// ---------------------------------------------------------------------------
// CSR build: exclusive scan of edge counts (deg-1), then cursor fill.
// ---------------------------------------------------------------------------
__global__ void k_scan1(const int* __restrict__ deg, int* __restrict__ rowptr,
                        int* __restrict__ bsum) {
    __shared__ int s[512];
    int tid = threadIdx.x;
    int i = blockIdx.x * 512 + tid;
    int v = (i < NN) ? (deg[i] - 1) : 0;
    s[tid] = v;
    __syncthreads();
    for (int o = 1; o < 512; o <<= 1) {
        int t = (tid >= o) ? s[tid - o] : 0;
        __syncthreads();
        s[tid] += t;
        __syncthreads();
    }
    if (i < NN) rowptr[i] = s[tid] - v;
    if (tid == 511) bsum[blockIdx.x] = s[511];
}
__global__ void k_scan2(int* __restrict__ bsum) {
    if (threadIdx.x == 0 && blockIdx.x == 0) {
        int acc = 0;
        for (int i = 0; i < NB; i++) { int v = bsum[i]; bsum[i] = acc; acc += v; }
    }
}
__global__ void k_scan3(int* __restrict__ rowptr, const int* __restrict__ bsum,
                        int* __restrict__ cursor) {
    int i = blockIdx.x * 512 + threadIdx.x;
    if (i < NN) {
        int r = rowptr[i] + bsum[blockIdx.x];
        rowptr[i] = r;
        cursor[i] = r;
    }
    if (blockIdx.x == 0 && threadIdx.x == 0) rowptr[NN] = NE;
}
__global__ void k_fill(const int* __restrict__ ei, int* __restrict__ cursor,
                       int* __restrict__ csr) {
    int e = blockIdx.x * blockDim.x + threadIdx.x;
    if (e >= NE) return;
    int dst = ei[NE + e];
    int pos = atomicAdd(&cursor[dst], 1);
    csr[pos] = ei[e];
}

// ---------------------------------------------------------------------------
// GEMM 128x128: out[row] = fp16( (A[row] @ W) [* scale[row]] )
// 512 threads, thread tile 8 rows x 4 cols, FFMA2 (fma.rn.f32x2) inner loop.
// ---------------------------------------------------------------------------
#define FFMA2(d, a, b) asm("fma.rn.f32x2 %0, %1, %2, %0;" : "+l"(d) : "l"(a), "l"(b))
#define PACK2(d, a)    asm("mov.b64 %0, {%1, %1};" : "=l"(d) : "f"(a))
union U64F2 { unsigned long long u; float2 f; };

static constexpr int GM_WS  = 0;
static constexpr int GM_AT  = 128 * 128;
static constexpr int GM_STG = 2 * 128 * 128;
static constexpr int GM_SMEM_FLOATS = 2 * 128 * 128 + 128 * 129;
static constexpr int GM_SMEM_BYTES  = GM_SMEM_FLOATS * 4;   // 197120

__global__ void __launch_bounds__(512, 1)
k_gemm128(const float* __restrict__ A, const float* __restrict__ W,
          const float* __restrict__ scale, __half* __restrict__ out, int nrows) {
    extern __shared__ float sm[];
    float* Ws  = sm + GM_WS;
    float* At  = sm + GM_AT;
    float* Stg = sm + GM_STG;

    const int tid  = threadIdx.x;
    const int row0 = blockIdx.x * 128;

    {
        const float4* w4 = (const float4*)W;
        float4* s4 = (float4*)Ws;
        for (int i = tid; i < 4096; i += 512) s4[i] = w4[i];
    }
    for (int i = tid; i < 4096; i += 512) {
        int r = i >> 5, kq = i & 31;
        int grow = row0 + r;
        float4 f = make_float4(0.f, 0.f, 0.f, 0.f);
        if (grow < nrows) f = ((const float4*)A)[(size_t)grow * 32 + kq];
        float* p = Stg + r * 129 + kq * 4;
        p[0] = f.x; p[1] = f.y; p[2] = f.z; p[3] = f.w;
    }
    __syncthreads();
    for (int i = tid; i < 16384; i += 512) {
        int r = i & 127, k = i >> 7;
        At[k * 128 + r] = Stg[r * 129 + k];
    }
    __syncthreads();

    const int tc = tid & 31;
    const int tr = tid >> 5;

    unsigned long long acc[8][2];
#pragma unroll
    for (int i = 0; i < 8; i++) { acc[i][0] = 0ull; acc[i][1] = 0ull; }

    const float* Wp = Ws + 4 * tc;
    const float* Ap = At + 8 * tr;

#pragma unroll 4
    for (int k = 0; k < 128; k++) {
        ulonglong2 wv = *(const ulonglong2*)(Wp + k * 128);
        float4 a0 = *(const float4*)(Ap + k * 128);
        float4 a1 = *(const float4*)(Ap + k * 128 + 4);
        unsigned long long p0, p1, p2, p3, p4, p5, p6, p7;
        PACK2(p0, a0.x); PACK2(p1, a0.y); PACK2(p2, a0.z); PACK2(p3, a0.w);
        PACK2(p4, a1.x); PACK2(p5, a1.y); PACK2(p6, a1.z); PACK2(p7, a1.w);
        FFMA2(acc[0][0], p0, wv.x); FFMA2(acc[0][1], p0, wv.y);
        FFMA2(acc[1][0], p1, wv.x); FFMA2(acc[1][1], p1, wv.y);
        FFMA2(acc[2][0], p2, wv.x); FFMA2(acc[2][1], p2, wv.y);
        FFMA2(acc[3][0], p3, wv.x); FFMA2(acc[3][1], p3, wv.y);
        FFMA2(acc[4][0], p4, wv.x); FFMA2(acc[4][1], p4, wv.y);
        FFMA2(acc[5][0], p5, wv.x); FFMA2(acc[5][1], p5, wv.y);
        FFMA2(acc[6][0], p6, wv.x); FFMA2(acc[6][1], p6, wv.y);
        FFMA2(acc[7][0], p7, wv.x); FFMA2(acc[7][1], p7, wv.y);
    }

#pragma unroll
    for (int i = 0; i < 8; i++) {
        int row = row0 + 8 * tr + i;
        if (row < nrows) {
            float s = scale ? scale[row] : 1.0f;
            U64F2 u0, u1;
            u0.u = acc[i][0];
            u1.u = acc[i][1];
            __half2 h0 = __floats2half2_rn(u0.f.x * s, u0.f.y * s);
            __half2 h1 = __floats2half2_rn(u1.f.x * s, u1.f.y * s);
            uint2 pk = make_uint2(*(uint32_t*)&h0, *(uint32_t*)&h1);
            ((uint2*)(out + (size_t)row * 128))[tc] = pk;
        }
    }
}

// ---------------------------------------------------------------------------
// Aggregate (CSR gather of fp16 rows): HALF-WARP per node, 2 nodes per warp.
// Lane (0..15) owns 8 halves (16B uint4) of the 256B row -> one LDG.128 per
// row per half-warp; 2-wide edge unroll => 4 rows in flight per warp.
// fp32 accumulation; fused self-loop + dinv + bias + relu.
// ---------------------------------------------------------------------------
struct F8 { float v[8]; };
__device__ __forceinline__ F8 h8f8(uint4 r) {
    F8 o;
    __half2 h0 = *(__half2*)&r.x, h1 = *(__half2*)&r.y;
    __half2 h2 = *(__half2*)&r.z, h3 = *(__half2*)&r.w;
    float2 f0 = __half22float2(h0), f1 = __half22float2(h1);
    float2 f2 = __half22float2(h2), f3 = __half22float2(h3);
    o.v[0] = f0.x; o.v[1] = f0.y; o.v[2] = f1.x; o.v[3] = f1.y;
    o.v[4] = f2.x; o.v[5] = f2.y; o.v[6] = f3.x; o.v[7] = f3.y;
    return o;
}

__global__ void k_agg(const int* __restrict__ rowptr, const int* __restrict__ csr,
                      const __half* __restrict__ tmp, const float* __restrict__ dinv,
                      const float* __restrict__ edinv, const float* __restrict__ bias,
                      float* __restrict__ out, int n0, int ncnt) {
    int hw = (blockIdx.x * blockDim.x + threadIdx.x) >> 4;   // half-warp id
    if (hw >= ncnt) return;
    int w = n0 + hw;
    int lane = threadIdx.x & 15;
    const uint4* t4 = (const uint4*)tmp;   // 16 uint4 per 128-half row

    float a[8], a2[8];
    {
        F8 self = h8f8(t4[(size_t)w * 16 + lane]);
        float se = edinv ? edinv[w] : 1.0f;
#pragma unroll
        for (int i = 0; i < 8; i++) { a[i] = self.v[i] * se; a2[i] = 0.0f; }
    }

    int e   = __ldg(rowptr + w);
    int end = __ldg(rowptr + w + 1);

    if (edinv) {
        for (; e + 1 < end; e += 2) {
            int s0 = __ldg(csr + e), s1 = __ldg(csr + e + 1);
            float e0 = __ldg(edinv + s0), e1 = __ldg(edinv + s1);
            uint4 r0 = t4[(size_t)s0 * 16 + lane];
            uint4 r1 = t4[(size_t)s1 * 16 + lane];
            F8 v0 = h8f8(r0), v1 = h8f8(r1);
#pragma unroll
            for (int i = 0; i < 8; i++) {
                a[i]  = fmaf(v0.v[i], e0, a[i]);
                a2[i] = fmaf(v1.v[i], e1, a2[i]);
            }
        }
        if (e < end) {
            int s0 = __ldg(csr + e);
            float e0 = __ldg(edinv + s0);
            F8 v0 = h8f8(t4[(size_t)s0 * 16 + lane]);
#pragma unroll
            for (int i = 0; i < 8; i++) a[i] = fmaf(v0.v[i], e0, a[i]);
        }
    } else {
        for (; e + 1 < end; e += 2) {
            int s0 = __ldg(csr + e), s1 = __ldg(csr + e + 1);
            uint4 r0 = t4[(size_t)s0 * 16 + lane];
            uint4 r1 = t4[(size_t)s1 * 16 + lane];
            F8 v0 = h8f8(r0), v1 = h8f8(r1);
#pragma unroll
            for (int i = 0; i < 8; i++) { a[i] += v0.v[i]; a2[i] += v1.v[i]; }
        }
        if (e < end) {
            int s0 = __ldg(csr + e);
            F8 v0 = h8f8(t4[(size_t)s0 * 16 + lane]);
#pragma unroll
            for (int i = 0; i < 8; i++) a[i] += v0.v[i];
        }
    }

    float sc = dinv[w];
    const float4* b4 = (const float4*)bias;
    float4 b0 = b4[lane * 2], b1 = b4[lane * 2 + 1];
    float4 o0, o1;
    o0.x = fmaxf(fmaf(a[0] + a2[0], sc, b0.x), 0.0f);
    o0.y = fmaxf(fmaf(a[1] + a2[1], sc, b0.y), 0.0f);
    o0.z = fmaxf(fmaf(a[2] + a2[2], sc, b0.z), 0.0f);
    o0.w = fmaxf(fmaf(a[3] + a2[3], sc, b0.w), 0.0f);
    o1.x = fmaxf(fmaf(a[4] + a2[4], sc, b1.x), 0.0f);
    o1.y = fmaxf(fmaf(a[5] + a2[5], sc, b1.y), 0.0f);
    o1.z = fmaxf(fmaf(a[6] + a2[6], sc, b1.z), 0.0f);
    o1.w = fmaxf(fmaf(a[7] + a2[7], sc, b1.w), 0.0f);
    float4* o4 = (float4*)out;
    o4[(size_t)w * 32 + lane * 2]     = o0;
    o4[(size_t)w * 32 + lane * 2 + 1] = o1;
}

// ---------------------------------------------------------------------------
// Classifier SIMT GEMM (BN=40), FFMA2 path.
// ---------------------------------------------------------------------------
template <int BN>
__global__ void k_gemm_cls(const float* __restrict__ A, const float* __restrict__ W,
                           const float* __restrict__ bias,
                           float* __restrict__ out0, int nrows) {
    constexpr int BM = 64;
    constexpr int TX = BN / 4;
    constexpr int TY = BM / 4;
    constexpr int NT = TX * TY;

    extern __shared__ float fsm[];
    float*  Ws = fsm;
    float2* Ad = (float2*)(fsm + 128 * BN);
    float*  As = (float*)(Ad + 128 * BM);

    const int tid  = threadIdx.x;
    const int row0 = blockIdx.x * BM;

    for (int idx = tid; idx < 128 * BN; idx += NT) Ws[idx] = W[idx];
    for (int idx = tid; idx < BM * 128; idx += NT) {
        int r = idx >> 7, k = idx & 127;
        int gr = row0 + r;
        As[r * 129 + k] = (gr < nrows) ? A[(size_t)gr * 128 + k] : 0.0f;
    }
    __syncthreads();
    for (int idx = tid; idx < 128 * BM; idx += NT) {
        int r = idx % BM, k = idx / BM;
        float v = As[r * 129 + k];
        Ad[idx] = make_float2(v, v);
    }
    __syncthreads();

    const int tc = tid % TX, tr = tid / TX;
    unsigned long long acc[4][2];
#pragma unroll
    for (int r = 0; r < 4; r++) { acc[r][0] = 0ull; acc[r][1] = 0ull; }

    const float2* adp = Ad + 4 * tr;
    const float*  wsp = Ws + 4 * tc;

#pragma unroll 8
    for (int k = 0; k < 128; k++) {
        ulonglong2 av0 = *(const ulonglong2*)(adp + (size_t)k * BM);
        ulonglong2 av1 = *(const ulonglong2*)(adp + (size_t)k * BM + 2);
        ulonglong2 wv  = *(const ulonglong2*)(wsp + (size_t)k * BN);
        FFMA2(acc[0][0], av0.x, wv.x); FFMA2(acc[0][1], av0.x, wv.y);
        FFMA2(acc[1][0], av0.y, wv.x); FFMA2(acc[1][1], av0.y, wv.y);
        FFMA2(acc[2][0], av1.x, wv.x); FFMA2(acc[2][1], av1.x, wv.y);
        FFMA2(acc[3][0], av1.y, wv.x); FFMA2(acc[3][1], av1.y, wv.y);
    }

#pragma unroll
    for (int r = 0; r < 4; r++) {
        int row = row0 + 4 * tr + r;
        if (row >= nrows) break;
        U64F2 u0, u1;
        u0.u = acc[r][0];
        u1.u = acc[r][1];
        float4 v = make_float4(u0.f.x + bias[4 * tc + 0], u0.f.y + bias[4 * tc + 1],
                               u1.f.x + bias[4 * tc + 2], u1.f.y + bias[4 * tc + 3]);
        *(float4*)(out0 + (size_t)row * BN + 4 * tc) = v;
    }
}

// ---------------------------------------------------------------------------
extern "C" void kernel_launch(void* const* d_in, const int* in_sizes, int n_in,
                              void* d_out, int out_size) {
    const float* x  = (const float*)d_in[0];
    const int*   ei = (const int*)d_in[1];
    const float* W1 = (const float*)d_in[2];
    const float* b1 = (const float*)d_in[3];
    const float* W2 = (const float*)d_in[4];
    const float* b2 = (const float*)d_in[5];
    const float* W3 = (const float*)d_in[6];
    const float* b3 = (const float*)d_in[7];
    const float* Wc = (const float*)d_in[8];
    const float* bc = (const float*)d_in[9];

    float* out_logits = (float*)d_out;                    // [NN,40]
    float* out_h      = (float*)d_out + (size_t)NN * 40;  // [NN,128]

    __half *tmpA, *tmpB;
    float *h, *dinv;
    int *deg, *rowptr, *cursor, *csr, *bsum;
    cudaGetSymbolAddress((void**)&tmpA,   g_tmpA);
    cudaGetSymbolAddress((void**)&tmpB,   g_tmpB);
    cudaGetSymbolAddress((void**)&h,      g_h);
    cudaGetSymbolAddress((void**)&dinv,   g_dinv);
    cudaGetSymbolAddress((void**)&deg,    g_deg);
    cudaGetSymbolAddress((void**)&rowptr, g_rowptr);
    cudaGetSymbolAddress((void**)&cursor, g_cursor);
    cudaGetSymbolAddress((void**)&csr,    g_csr);
    cudaGetSymbolAddress((void**)&bsum,   g_bsum);

    const int SM40 = 128 * 40 * 4 + 128 * 64 * 8 + 64 * 129 * 4;
    cudaFuncSetAttribute(k_gemm128, cudaFuncAttributeMaxDynamicSharedMemorySize, GM_SMEM_BYTES);
    cudaFuncSetAttribute(k_gemm_cls<40>, cudaFuncAttributeMaxDynamicSharedMemorySize, SM40);

    cudaStream_t S = g_ctx.s;
    cudaEvent_t* E = g_ctx.e;

    // fork side stream off the capture (main) stream
    cudaEventRecord(E[0], 0);
    cudaStreamWaitEvent(S, E[0], 0);

    // ---- side stream: normalization + CSR build (hidden behind GEMM1) ----
    k_deg_init<<<(NN + 255) / 256, 256, 0, S>>>(deg);
    k_deg_count<<<(NE + 255) / 256, 256, 0, S>>>(ei, deg);
    k_dinv<<<(NN + 255) / 256, 256, 0, S>>>(deg, dinv);
    k_scan1<<<NB, 512, 0, S>>>(deg, rowptr, bsum);
    k_scan2<<<1, 32, 0, S>>>(bsum);
    k_scan3<<<NB, 512, 0, S>>>(rowptr, bsum, cursor);
    k_fill<<<(NE + 255) / 256, 256, 0, S>>>(ei, cursor, csr);
    cudaEventRecord(E[1], S);   // CSR + dinv ready

    // ---- main: layer 1 GEMM -> tmpA (unscaled; no dinv dependency) ----
    k_gemm128<<<(NN + 127) / 128, 512, GM_SMEM_BYTES>>>(x, W1, nullptr, tmpA, NN);

    // agg layer 1 reads tmpA (dinv[src] per edge), writes h   [16 nodes/block]
    cudaStreamWaitEvent(0, E[1], 0);
    k_agg<<<HA / 16, 256>>>(rowptr, csr, tmpA, dinv, dinv, b1, h, 0, HA);
    cudaEventRecord(E[2], 0);   // h rows [0,HA) ready
    k_agg<<<HB / 16, 256>>>(rowptr, csr, tmpA, dinv, dinv, b1, h, HA, HB);

    // side: GEMM2-A (reads h[0:HA), writes tmpB) overlaps agg1-B (reads tmpA)
    cudaStreamWaitEvent(S, E[2], 0);
    k_gemm128<<<HA / 128, 512, GM_SMEM_BYTES, S>>>(h, W2, dinv, tmpB, HA);
    cudaEventRecord(E[3], S);
    // main: GEMM2-B
    k_gemm128<<<(HB + 127) / 128, 512, GM_SMEM_BYTES>>>(h + (size_t)HA * 128, W2,
                                                        dinv + HA, tmpB + (size_t)HA * 128, HB);
    cudaStreamWaitEvent(0, E[3], 0);
    // agg layer 2 reads tmpB, writes h
    k_agg<<<HA / 16, 256>>>(rowptr, csr, tmpB, dinv, nullptr, b2, h, 0, HA);
    cudaEventRecord(E[4], 0);
    k_agg<<<HB / 16, 256>>>(rowptr, csr, tmpB, dinv, nullptr, b2, h, HA, HB);

    // side: GEMM3-A (reads h[0:HA), writes tmpA) overlaps agg2-B (reads tmpB)
    cudaStreamWaitEvent(S, E[4], 0);
    k_gemm128<<<HA / 128, 512, GM_SMEM_BYTES, S>>>(h, W3, dinv, tmpA, HA);
    cudaEventRecord(E[5], S);
    // main: GEMM3-B
    k_gemm128<<<(HB + 127) / 128, 512, GM_SMEM_BYTES>>>(h + (size_t)HA * 128, W3,
                                                        dinv + HA, tmpA + (size_t)HA * 128, HB);
    cudaStreamWaitEvent(0, E[5], 0);
    // agg layer 3 reads tmpA, writes out_h
    k_agg<<<HA / 16, 256>>>(rowptr, csr, tmpA, dinv, nullptr, b3, out_h, 0, HA);
    cudaEventRecord(E[6], 0);
    k_agg<<<HB / 16, 256>>>(rowptr, csr, tmpA, dinv, nullptr, b3, out_h, HA, HB);

    // side: classifier-A (reads out_h[0:HA)) overlaps agg3-B (writes out_h[HA:))
    cudaStreamWaitEvent(S, E[6], 0);
    k_gemm_cls<40><<<HA / 64, 160, SM40, S>>>(out_h, Wc, bc, out_logits, HA);
    cudaEventRecord(E[7], S);
    // main: classifier-B
    k_gemm_cls<40><<<(HB + 63) / 64, 160, SM40>>>(out_h + (size_t)HA * 128, Wc, bc,
                                                  out_logits + (size_t)HA * 40, HB);
    // join side stream back into main before capture ends
    cudaStreamWaitEvent(0, E[7], 0);
}

// round 9
// speedup vs baseline: 1.0815x; 1.0064x over previous
#include <cuda_runtime.h>
#include <cuda_fp16.h>
#include <cstdint>

#define NN 50000
#define NE 800000
#define NB 98        // scan blocks: 98*512 >= 50000
#define HA 25088     // first-half nodes (multiple of 128, 64, 16)
#define HB (NN - HA) // 24912 (multiple of 16)

// ---------------------------------------------------------------------------
// Scratch (static device arrays: allocation-free per harness rules)
// ---------------------------------------------------------------------------
__device__ __half g_tmpA[NN * 128];
__device__ __half g_tmpB[NN * 128];
__device__ float  g_h[NN * 128];
__device__ float  g_dinv[NN];
__device__ int    g_deg[NN];
__device__ int    g_rowptr[NN + 1];
__device__ int    g_cursor[NN];
__device__ int    g_csr[NE];
__device__ int    g_bsum[NB];

// ---------------------------------------------------------------------------
// Host-side stream/event context (host resources only; created at static init)
// ---------------------------------------------------------------------------
struct Ctx {
    cudaStream_t s;
    cudaEvent_t e[12];
    Ctx() {
        cudaStreamCreateWithFlags(&s, cudaStreamNonBlocking);
        for (int i = 0; i < 12; i++) cudaEventCreateWithFlags(&e[i], cudaEventDisableTiming);
    }
};
static Ctx g_ctx;

// ---------------------------------------------------------------------------
// degree / normalization
// ---------------------------------------------------------------------------
__global__ void k_deg_init(int* __restrict__ deg) {
    int i = blockIdx.x * blockDim.x + threadIdx.x;
    if (i < NN) deg[i] = 1;  // self-loop
}
__global__ void k_deg_count(const int* __restrict__ ei, int* __restrict__ deg) {
    int e = blockIdx.x * blockDim.x + threadIdx.x;
    if (e < NE) atomicAdd(&deg[ei[NE + e]], 1);
}
__global__ void k_dinv(const int* __restrict__ deg, float* __restrict__ dinv) {
    int i = blockIdx.x * blockDim.x + threadIdx.x;
    if (i < NN) dinv[i] = rsqrtf((float)deg[i]);
}

// ---------------------------------------------------------------------------
// CSR build: exclusive scan of edge counts (deg-1), then cursor fill.
// ---------------------------------------------------------------------------
__global__ void k_scan1(const int* __restrict__ deg, int* __restrict__ rowptr,
                        int* __restrict__ bsum) {
    __shared__ int s[512];
    int tid = threadIdx.x;
    int i = blockIdx.x * 512 + tid;
    int v = (i < NN) ? (deg[i] - 1) : 0;
    s[tid] = v;
    __syncthreads();
    for (int o = 1; o < 512; o <<= 1) {
        int t = (tid >= o) ? s[tid - o] : 0;
        __syncthreads();
        s[tid] += t;
        __syncthreads();
    }
    if (i < NN) rowptr[i] = s[tid] - v;
    if (tid == 511) bsum[blockIdx.x] = s[511];
}
__global__ void k_scan2(int* __restrict__ bsum) {
    if (threadIdx.x == 0 && blockIdx.x == 0) {
        int acc = 0;
        for (int i = 0; i < NB; i++) { int v = bsum[i]; bsum[i] = acc; acc += v; }
    }
}
__global__ void k_scan3(int* __restrict__ rowptr, const int* __restrict__ bsum,
                        int* __restrict__ cursor) {
    int i = blockIdx.x * 512 + threadIdx.x;
    if (i < NN) {
        int r = rowptr[i] + bsum[blockIdx.x];
        rowptr[i] = r;
        cursor[i] = r;
    }
    if (blockIdx.x == 0 && threadIdx.x == 0) rowptr[NN] = NE;
}
__global__ void k_fill(const int* __restrict__ ei, int* __restrict__ cursor,
                       int* __restrict__ csr) {
    int e = blockIdx.x * blockDim.x + threadIdx.x;
    if (e >= NE) return;
    int dst = ei[NE + e];
    int pos = atomicAdd(&cursor[dst], 1);
    csr[pos] = ei[e];
}

// ---------------------------------------------------------------------------
// GEMM 128x128: out[row] = fp16( (A[row] @ W) [* scale[row]] )
// 512 threads, thread tile 8 rows x 4 cols, FFMA2 (fma.rn.f32x2) inner loop.
// ---------------------------------------------------------------------------
#define FFMA2(d, a, b) asm("fma.rn.f32x2 %0, %1, %2, %0;" : "+l"(d) : "l"(a), "l"(b))
#define PACK2(d, a)    asm("mov.b64 %0, {%1, %1};" : "=l"(d) : "f"(a))
union U64F2 { unsigned long long u; float2 f; };

static constexpr int GM_WS  = 0;
static constexpr int GM_AT  = 128 * 128;
static constexpr int GM_STG = 2 * 128 * 128;
static constexpr int GM_SMEM_FLOATS = 2 * 128 * 128 + 128 * 129;
static constexpr int GM_SMEM_BYTES  = GM_SMEM_FLOATS * 4;   // 197120

__global__ void __launch_bounds__(512, 1)
k_gemm128(const float* __restrict__ A, const float* __restrict__ W,
          const float* __restrict__ scale, __half* __restrict__ out, int nrows) {
    extern __shared__ float sm[];
    float* Ws  = sm + GM_WS;
    float* At  = sm + GM_AT;
    float* Stg = sm + GM_STG;

    const int tid  = threadIdx.x;
    const int row0 = blockIdx.x * 128;

    {
        const float4* w4 = (const float4*)W;
        float4* s4 = (float4*)Ws;
        for (int i = tid; i < 4096; i += 512) s4[i] = w4[i];
    }
    for (int i = tid; i < 4096; i += 512) {
        int r = i >> 5, kq = i & 31;
        int grow = row0 + r;
        float4 f = make_float4(0.f, 0.f, 0.f, 0.f);
        if (grow < nrows) f = ((const float4*)A)[(size_t)grow * 32 + kq];
        float* p = Stg + r * 129 + kq * 4;
        p[0] = f.x; p[1] = f.y; p[2] = f.z; p[3] = f.w;
    }
    __syncthreads();
    for (int i = tid; i < 16384; i += 512) {
        int r = i & 127, k = i >> 7;
        At[k * 128 + r] = Stg[r * 129 + k];
    }
    __syncthreads();

    const int tc = tid & 31;
    const int tr = tid >> 5;

    unsigned long long acc[8][2];
#pragma unroll
    for (int i = 0; i < 8; i++) { acc[i][0] = 0ull; acc[i][1] = 0ull; }

    const float* Wp = Ws + 4 * tc;
    const float* Ap = At + 8 * tr;

#pragma unroll 4
    for (int k = 0; k < 128; k++) {
        ulonglong2 wv = *(const ulonglong2*)(Wp + k * 128);
        float4 a0 = *(const float4*)(Ap + k * 128);
        float4 a1 = *(const float4*)(Ap + k * 128 + 4);
        unsigned long long p0, p1, p2, p3, p4, p5, p6, p7;
        PACK2(p0, a0.x); PACK2(p1, a0.y); PACK2(p2, a0.z); PACK2(p3, a0.w);
        PACK2(p4, a1.x); PACK2(p5, a1.y); PACK2(p6, a1.z); PACK2(p7, a1.w);
        FFMA2(acc[0][0], p0, wv.x); FFMA2(acc[0][1], p0, wv.y);
        FFMA2(acc[1][0], p1, wv.x); FFMA2(acc[1][1], p1, wv.y);
        FFMA2(acc[2][0], p2, wv.x); FFMA2(acc[2][1], p2, wv.y);
        FFMA2(acc[3][0], p3, wv.x); FFMA2(acc[3][1], p3, wv.y);
        FFMA2(acc[4][0], p4, wv.x); FFMA2(acc[4][1], p4, wv.y);
        FFMA2(acc[5][0], p5, wv.x); FFMA2(acc[5][1], p5, wv.y);
        FFMA2(acc[6][0], p6, wv.x); FFMA2(acc[6][1], p6, wv.y);
        FFMA2(acc[7][0], p7, wv.x); FFMA2(acc[7][1], p7, wv.y);
    }

#pragma unroll
    for (int i = 0; i < 8; i++) {
        int row = row0 + 8 * tr + i;
        if (row < nrows) {
            float s = scale ? scale[row] : 1.0f;
            U64F2 u0, u1;
            u0.u = acc[i][0];
            u1.u = acc[i][1];
            __half2 h0 = __floats2half2_rn(u0.f.x * s, u0.f.y * s);
            __half2 h1 = __floats2half2_rn(u1.f.x * s, u1.f.y * s);
            uint2 pk = make_uint2(*(uint32_t*)&h0, *(uint32_t*)&h1);
            ((uint2*)(out + (size_t)row * 128))[tc] = pk;
        }
    }
}

// ---------------------------------------------------------------------------
// Aggregate (CSR gather of fp16 rows): HALF-WARP per node, 2 nodes per warp.
// Lane (0..15) owns 8 halves (16B uint4) of the 256B row -> one LDG.128 per
// row per half-warp; 2-wide edge unroll => 4 rows in flight per warp.
// fp32 accumulation; fused self-loop + dinv + bias + relu.
// ---------------------------------------------------------------------------
struct F8 { float v[8]; };
__device__ __forceinline__ F8 h8f8(uint4 r) {
    F8 o;
    __half2 h0 = *(__half2*)&r.x, h1 = *(__half2*)&r.y;
    __half2 h2 = *(__half2*)&r.z, h3 = *(__half2*)&r.w;
    float2 f0 = __half22float2(h0), f1 = __half22float2(h1);
    float2 f2 = __half22float2(h2), f3 = __half22float2(h3);
    o.v[0] = f0.x; o.v[1] = f0.y; o.v[2] = f1.x; o.v[3] = f1.y;
    o.v[4] = f2.x; o.v[5] = f2.y; o.v[6] = f3.x; o.v[7] = f3.y;
    return o;
}

__global__ void k_agg(const int* __restrict__ rowptr, const int* __restrict__ csr,
                      const __half* __restrict__ tmp, const float* __restrict__ dinv,
                      const float* __restrict__ edinv, const float* __restrict__ bias,
                      float* __restrict__ out, int n0, int ncnt) {
    int hw = (blockIdx.x * blockDim.x + threadIdx.x) >> 4;   // half-warp id
    if (hw >= ncnt) return;
    int w = n0 + hw;
    int lane = threadIdx.x & 15;
    const uint4* t4 = (const uint4*)tmp;   // 16 uint4 per 128-half row

    float a[8], a2[8];
    {
        F8 self = h8f8(t4[(size_t)w * 16 + lane]);
        float se = edinv ? edinv[w] : 1.0f;
#pragma unroll
        for (int i = 0; i < 8; i++) { a[i] = self.v[i] * se; a2[i] = 0.0f; }
    }

    int e   = __ldg(rowptr + w);
    int end = __ldg(rowptr + w + 1);

    if (edinv) {
        for (; e + 1 < end; e += 2) {
            int s0 = __ldg(csr + e), s1 = __ldg(csr + e + 1);
            float e0 = __ldg(edinv + s0), e1 = __ldg(edinv + s1);
            uint4 r0 = t4[(size_t)s0 * 16 + lane];
            uint4 r1 = t4[(size_t)s1 * 16 + lane];
            F8 v0 = h8f8(r0), v1 = h8f8(r1);
#pragma unroll
            for (int i = 0; i < 8; i++) {
                a[i]  = fmaf(v0.v[i], e0, a[i]);
                a2[i] = fmaf(v1.v[i], e1, a2[i]);
            }
        }
        if (e < end) {
            int s0 = __ldg(csr + e);
            float e0 = __ldg(edinv + s0);
            F8 v0 = h8f8(t4[(size_t)s0 * 16 + lane]);
#pragma unroll
            for (int i = 0; i < 8; i++) a[i] = fmaf(v0.v[i], e0, a[i]);
        }
    } else {
        for (; e + 1 < end; e += 2) {
            int s0 = __ldg(csr + e), s1 = __ldg(csr + e + 1);
            uint4 r0 = t4[(size_t)s0 * 16 + lane];
            uint4 r1 = t4[(size_t)s1 * 16 + lane];
            F8 v0 = h8f8(r0), v1 = h8f8(r1);
#pragma unroll
            for (int i = 0; i < 8; i++) { a[i] += v0.v[i]; a2[i] += v1.v[i]; }
        }
        if (e < end) {
            int s0 = __ldg(csr + e);
            F8 v0 = h8f8(t4[(size_t)s0 * 16 + lane]);
#pragma unroll
            for (int i = 0; i < 8; i++) a[i] += v0.v[i];
        }
    }

    float sc = dinv[w];
    const float4* b4 = (const float4*)bias;
    float4 b0 = b4[lane * 2], b1 = b4[lane * 2 + 1];
    float4 o0, o1;
    o0.x = fmaxf(fmaf(a[0] + a2[0], sc, b0.x), 0.0f);
    o0.y = fmaxf(fmaf(a[1] + a2[1], sc, b0.y), 0.0f);
    o0.z = fmaxf(fmaf(a[2] + a2[2], sc, b0.z), 0.0f);
    o0.w = fmaxf(fmaf(a[3] + a2[3], sc, b0.w), 0.0f);
    o1.x = fmaxf(fmaf(a[4] + a2[4], sc, b1.x), 0.0f);
    o1.y = fmaxf(fmaf(a[5] + a2[5], sc, b1.y), 0.0f);
    o1.z = fmaxf(fmaf(a[6] + a2[6], sc, b1.z), 0.0f);
    o1.w = fmaxf(fmaf(a[7] + a2[7], sc, b1.w), 0.0f);
    float4* o4 = (float4*)out;
    o4[(size_t)w * 32 + lane * 2]     = o0;
    o4[(size_t)w * 32 + lane * 2 + 1] = o1;
}

// ---------------------------------------------------------------------------
// Classifier SIMT GEMM (BN=40), FFMA2 path.
// ---------------------------------------------------------------------------
template <int BN>
__global__ void k_gemm_cls(const float* __restrict__ A, const float* __restrict__ W,
                           const float* __restrict__ bias,
                           float* __restrict__ out0, int nrows) {
    constexpr int BM = 64;
    constexpr int TX = BN / 4;
    constexpr int TY = BM / 4;
    constexpr int NT = TX * TY;

    extern __shared__ float fsm[];
    float*  Ws = fsm;
    float2* Ad = (float2*)(fsm + 128 * BN);
    float*  As = (float*)(Ad + 128 * BM);

    const int tid  = threadIdx.x;
    const int row0 = blockIdx.x * BM;

    for (int idx = tid; idx < 128 * BN; idx += NT) Ws[idx] = W[idx];
    for (int idx = tid; idx < BM * 128; idx += NT) {
        int r = idx >> 7, k = idx & 127;
        int gr = row0 + r;
        As[r * 129 + k] = (gr < nrows) ? A[(size_t)gr * 128 + k] : 0.0f;
    }
    __syncthreads();
    for (int idx = tid; idx < 128 * BM; idx += NT) {
        int r = idx % BM, k = idx / BM;
        float v = As[r * 129 + k];
        Ad[idx] = make_float2(v, v);
    }
    __syncthreads();

    const int tc = tid % TX, tr = tid / TX;
    unsigned long long acc[4][2];
#pragma unroll
    for (int r = 0; r < 4; r++) { acc[r][0] = 0ull; acc[r][1] = 0ull; }

    const float2* adp = Ad + 4 * tr;
    const float*  wsp = Ws + 4 * tc;

#pragma unroll 8
    for (int k = 0; k < 128; k++) {
        ulonglong2 av0 = *(const ulonglong2*)(adp + (size_t)k * BM);
        ulonglong2 av1 = *(const ulonglong2*)(adp + (size_t)k * BM + 2);
        ulonglong2 wv  = *(const ulonglong2*)(wsp + (size_t)k * BN);
        FFMA2(acc[0][0], av0.x, wv.x); FFMA2(acc[0][1], av0.x, wv.y);
        FFMA2(acc[1][0], av0.y, wv.x); FFMA2(acc[1][1], av0.y, wv.y);
        FFMA2(acc[2][0], av1.x, wv.x); FFMA2(acc[2][1], av1.x, wv.y);
        FFMA2(acc[3][0], av1.y, wv.x); FFMA2(acc[3][1], av1.y, wv.y);
    }

#pragma unroll
    for (int r = 0; r < 4; r++) {
        int row = row0 + 4 * tr + r;
        if (row >= nrows) break;
        U64F2 u0, u1;
        u0.u = acc[r][0];
        u1.u = acc[r][1];
        float4 v = make_float4(u0.f.x + bias[4 * tc + 0], u0.f.y + bias[4 * tc + 1],
                               u1.f.x + bias[4 * tc + 2], u1.f.y + bias[4 * tc + 3]);
        *(float4*)(out0 + (size_t)row * BN + 4 * tc) = v;
    }
}

// ---------------------------------------------------------------------------
extern "C" void kernel_launch(void* const* d_in, const int* in_sizes, int n_in,
                              void* d_out, int out_size) {
    const float* x  = (const float*)d_in[0];
    const int*   ei = (const int*)d_in[1];
    const float* W1 = (const float*)d_in[2];
    const float* b1 = (const float*)d_in[3];
    const float* W2 = (const float*)d_in[4];
    const float* b2 = (const float*)d_in[5];
    const float* W3 = (const float*)d_in[6];
    const float* b3 = (const float*)d_in[7];
    const float* Wc = (const float*)d_in[8];
    const float* bc = (const float*)d_in[9];

    float* out_logits = (float*)d_out;                    // [NN,40]
    float* out_h      = (float*)d_out + (size_t)NN * 40;  // [NN,128]

    __half *tmpA, *tmpB;
    float *h, *dinv;
    int *deg, *rowptr, *cursor, *csr, *bsum;
    cudaGetSymbolAddress((void**)&tmpA,   g_tmpA);
    cudaGetSymbolAddress((void**)&tmpB,   g_tmpB);
    cudaGetSymbolAddress((void**)&h,      g_h);
    cudaGetSymbolAddress((void**)&dinv,   g_dinv);
    cudaGetSymbolAddress((void**)&deg,    g_deg);
    cudaGetSymbolAddress((void**)&rowptr, g_rowptr);
    cudaGetSymbolAddress((void**)&cursor, g_cursor);
    cudaGetSymbolAddress((void**)&csr,    g_csr);
    cudaGetSymbolAddress((void**)&bsum,   g_bsum);

    const int SM40 = 128 * 40 * 4 + 128 * 64 * 8 + 64 * 129 * 4;
    cudaFuncSetAttribute(k_gemm128, cudaFuncAttributeMaxDynamicSharedMemorySize, GM_SMEM_BYTES);
    cudaFuncSetAttribute(k_gemm_cls<40>, cudaFuncAttributeMaxDynamicSharedMemorySize, SM40);

    cudaStream_t S = g_ctx.s;
    cudaEvent_t* E = g_ctx.e;

    // fork side stream off the capture (main) stream
    cudaEventRecord(E[0], 0);
    cudaStreamWaitEvent(S, E[0], 0);

    // ---- side stream: normalization + CSR build (hidden behind GEMM1) ----
    k_deg_init<<<(NN + 255) / 256, 256, 0, S>>>(deg);
    k_deg_count<<<(NE + 255) / 256, 256, 0, S>>>(ei, deg);
    k_dinv<<<(NN + 255) / 256, 256, 0, S>>>(deg, dinv);
    k_scan1<<<NB, 512, 0, S>>>(deg, rowptr, bsum);
    k_scan2<<<1, 32, 0, S>>>(bsum);
    k_scan3<<<NB, 512, 0, S>>>(rowptr, bsum, cursor);
    k_fill<<<(NE + 255) / 256, 256, 0, S>>>(ei, cursor, csr);
    cudaEventRecord(E[1], S);   // CSR + dinv ready

    // ---- main: layer 1 GEMM -> tmpA (unscaled; no dinv dependency) ----
    k_gemm128<<<(NN + 127) / 128, 512, GM_SMEM_BYTES>>>(x, W1, nullptr, tmpA, NN);

    // agg layer 1 reads tmpA (dinv[src] per edge), writes h   [16 nodes/block]
    cudaStreamWaitEvent(0, E[1], 0);
    k_agg<<<HA / 16, 256>>>(rowptr, csr, tmpA, dinv, dinv, b1, h, 0, HA);
    cudaEventRecord(E[2], 0);   // h rows [0,HA) ready
    k_agg<<<HB / 16, 256>>>(rowptr, csr, tmpA, dinv, dinv, b1, h, HA, HB);

    // side: GEMM2-A (reads h[0:HA), writes tmpB) overlaps agg1-B (reads tmpA)
    cudaStreamWaitEvent(S, E[2], 0);
    k_gemm128<<<HA / 128, 512, GM_SMEM_BYTES, S>>>(h, W2, dinv, tmpB, HA);
    cudaEventRecord(E[3], S);
    // main: GEMM2-B
    k_gemm128<<<(HB + 127) / 128, 512, GM_SMEM_BYTES>>>(h + (size_t)HA * 128, W2,
                                                        dinv + HA, tmpB + (size_t)HA * 128, HB);
    cudaStreamWaitEvent(0, E[3], 0);
    // agg layer 2 reads tmpB, writes h
    k_agg<<<HA / 16, 256>>>(rowptr, csr, tmpB, dinv, nullptr, b2, h, 0, HA);
    cudaEventRecord(E[4], 0);
    k_agg<<<HB / 16, 256>>>(rowptr, csr, tmpB, dinv, nullptr, b2, h, HA, HB);

    // side: GEMM3-A (reads h[0:HA), writes tmpA) overlaps agg2-B (reads tmpB)
    cudaStreamWaitEvent(S, E[4], 0);
    k_gemm128<<<HA / 128, 512, GM_SMEM_BYTES, S>>>(h, W3, dinv, tmpA, HA);
    cudaEventRecord(E[5], S);
    // main: GEMM3-B
    k_gemm128<<<(HB + 127) / 128, 512, GM_SMEM_BYTES>>>(h + (size_t)HA * 128, W3,
                                                        dinv + HA, tmpA + (size_t)HA * 128, HB);
    cudaStreamWaitEvent(0, E[5], 0);
    // agg layer 3 reads tmpA, writes out_h
    k_agg<<<HA / 16, 256>>>(rowptr, csr, tmpA, dinv, nullptr, b3, out_h, 0, HA);
    cudaEventRecord(E[6], 0);
    k_agg<<<HB / 16, 256>>>(rowptr, csr, tmpA, dinv, nullptr, b3, out_h, HA, HB);

    // side: classifier-A (reads out_h[0:HA)) overlaps agg3-B (writes out_h[HA:))
    cudaStreamWaitEvent(S, E[6], 0);
    k_gemm_cls<40><<<HA / 64, 160, SM40, S>>>(out_h, Wc, bc, out_logits, HA);
    cudaEventRecord(E[7], S);
    // main: classifier-B
    k_gemm_cls<40><<<(HB + 63) / 64, 160, SM40>>>(out_h + (size_t)HA * 128, Wc, bc,
                                                  out_logits + (size_t)HA * 40, HB);
    // join side stream back into main before capture ends
    cudaStreamWaitEvent(0, E[7], 0);
}

// round 10
// speedup vs baseline: 1.4984x; 1.3855x over previous
#include <cuda_runtime.h>
#include <cuda_fp16.h>
#include <cstdint>

#define NN 50000
#define NE 800000
#define NB 98        // scan blocks: 98*512 >= 50000
#define HA 25088     // first-half nodes (multiple of 128, 64, 16)
#define HB (NN - HA) // 24912 (multiple of 16)

// ---------------------------------------------------------------------------
// Scratch (static device arrays: allocation-free per harness rules)
// ---------------------------------------------------------------------------
__device__ __half g_tmpA[NN * 128];
__device__ __half g_tmpB[NN * 128];
__device__ float  g_h[NN * 128];
__device__ float  g_dinv[NN];
__device__ int    g_deg[NN];
__device__ int    g_rowptr[NN + 1];
__device__ int    g_cursor[NN];
__device__ int    g_csr[NE];
__device__ int    g_bsum[NB];

// ---------------------------------------------------------------------------
// Host-side stream/event context (host resources only; created at static init)
// ---------------------------------------------------------------------------
struct Ctx {
    cudaStream_t s;
    cudaEvent_t e[12];
    Ctx() {
        cudaStreamCreateWithFlags(&s, cudaStreamNonBlocking);
        for (int i = 0; i < 12; i++) cudaEventCreateWithFlags(&e[i], cudaEventDisableTiming);
    }
};
static Ctx g_ctx;

// ---------------------------------------------------------------------------
// degree / normalization
// ---------------------------------------------------------------------------
__global__ void k_deg_init(int* __restrict__ deg) {
    int i = blockIdx.x * blockDim.x + threadIdx.x;
    if (i < NN) deg[i] = 1;  // self-loop
}
__global__ void k_deg_count(const int* __restrict__ ei, int* __restrict__ deg) {
    int e = blockIdx.x * blockDim.x + threadIdx.x;
    if (e < NE) atomicAdd(&deg[ei[NE + e]], 1);
}

// ---------------------------------------------------------------------------
// CSR build: scan1 (block-local exclusive scan + dinv), scan3 (+cross-block
// base reduction, fused old scan2), cursor fill.
// ---------------------------------------------------------------------------
__global__ void k_scan1(const int* __restrict__ deg, int* __restrict__ rowptr,
                        int* __restrict__ bsum, float* __restrict__ dinv) {
    __shared__ int s[512];
    int tid = threadIdx.x;
    int i = blockIdx.x * 512 + tid;
    int d = (i < NN) ? deg[i] : 1;
    if (i < NN) dinv[i] = rsqrtf((float)d);
    int v = (i < NN) ? (d - 1) : 0;
    s[tid] = v;
    __syncthreads();
    for (int o = 1; o < 512; o <<= 1) {
        int t = (tid >= o) ? s[tid - o] : 0;
        __syncthreads();
        s[tid] += t;
        __syncthreads();
    }
    if (i < NN) rowptr[i] = s[tid] - v;
    if (tid == 511) bsum[blockIdx.x] = s[511];
}
__global__ void k_scan3(int* __restrict__ rowptr, const int* __restrict__ bsum,
                        int* __restrict__ cursor) {
    __shared__ int sb[128];
    int tid = threadIdx.x;
    if (tid < 128) sb[tid] = (tid < blockIdx.x && tid < NB) ? bsum[tid] : 0;
    __syncthreads();
    for (int o = 64; o > 0; o >>= 1) {
        if (tid < o) sb[tid] += sb[tid + o];
        __syncthreads();
    }
    int base = sb[0];
    int i = blockIdx.x * 512 + tid;
    if (i < NN) {
        int r = rowptr[i] + base;
        rowptr[i] = r;
        cursor[i] = r;
    }
    if (blockIdx.x == 0 && tid == 0) rowptr[NN] = NE;
}
__global__ void k_fill(const int* __restrict__ ei, int* __restrict__ cursor,
                       int* __restrict__ csr) {
    int e = blockIdx.x * blockDim.x + threadIdx.x;
    if (e >= NE) return;
    int dst = ei[NE + e];
    int pos = atomicAdd(&cursor[dst], 1);
    csr[pos] = ei[e];
}

// ---------------------------------------------------------------------------
// Tensor-core GEMM (HMMA mma.sync, sm_80+-portable): 128x128 tile per block.
// out[row] = fp16( (A[row] @ W) [* scale[row]] ); fp32 accumulate.
// 8 warps; warp w owns rows [16w, 16w+16). A/W: fp32 gmem -> fp16 smem,
// row stride 136 halves (conflict-free ldmatrix).
// ---------------------------------------------------------------------------
static constexpr int MMA_SMEM_BYTES = 2 * 128 * 136 * 2;   // 69632

__global__ void __launch_bounds__(256)
k_gemm_mma(const float* __restrict__ A, const float* __restrict__ W,
           const float* __restrict__ scale, __half* __restrict__ out, int nrows) {
    extern __shared__ __half sh[];
    __half* As = sh;               // [128][136]
    __half* Bs = sh + 128 * 136;   // [128][136]  (W[k][n])
    const int tid = threadIdx.x;
    const int wid = tid >> 5, lane = tid & 31;
    const int row0 = blockIdx.x * 128;

    // W fp32 [k][n] -> Bs fp16
    for (int i = tid; i < 4096; i += 256) {
        int k = i >> 5, nq = i & 31;
        float4 f = ((const float4*)W)[i];
        __half* p = Bs + k * 136 + nq * 4;
        *(__half2*)p       = __floats2half2_rn(f.x, f.y);
        *(__half2*)(p + 2) = __floats2half2_rn(f.z, f.w);
    }
    // A fp32 [row][k] -> As fp16 (zero-fill OOB rows)
    for (int i = tid; i < 4096; i += 256) {
        int r = i >> 5, kq = i & 31;
        int grow = row0 + r;
        float4 f = make_float4(0.f, 0.f, 0.f, 0.f);
        if (grow < nrows) f = ((const float4*)A)[(size_t)grow * 32 + kq];
        __half* p = As + r * 136 + kq * 4;
        *(__half2*)p       = __floats2half2_rn(f.x, f.y);
        *(__half2*)(p + 2) = __floats2half2_rn(f.z, f.w);
    }
    __syncthreads();

    float cf[16][4];
#pragma unroll
    for (int t = 0; t < 16; t++) { cf[t][0] = cf[t][1] = cf[t][2] = cf[t][3] = 0.f; }

    const int wr0 = wid * 16;
    uint32_t a_base = (uint32_t)__cvta_generic_to_shared(
        As + (wr0 + (lane & 15)) * 136 + (lane >> 4) * 8);
    uint32_t b_base = (uint32_t)__cvta_generic_to_shared(
        Bs + (lane & 15) * 136 + (lane >> 4) * 8);

#pragma unroll
    for (int ks = 0; ks < 8; ks++) {
        uint32_t a0, a1, a2, a3;
        asm volatile("ldmatrix.sync.aligned.m8n8.x4.shared.b16 {%0,%1,%2,%3}, [%4];"
                     : "=r"(a0), "=r"(a1), "=r"(a2), "=r"(a3)
                     : "r"(a_base + ks * 16 * 2));
#pragma unroll
        for (int nt = 0; nt < 8; nt++) {
            uint32_t b0, b1, b2, b3;
            asm volatile("ldmatrix.sync.aligned.m8n8.x4.trans.shared.b16 {%0,%1,%2,%3}, [%4];"
                         : "=r"(b0), "=r"(b1), "=r"(b2), "=r"(b3)
                         : "r"(b_base + (ks * 16 * 136 + nt * 16) * 2));
            asm volatile(
                "mma.sync.aligned.m16n8k16.row.col.f32.f16.f16.f32 "
                "{%0,%1,%2,%3}, {%4,%5,%6,%7}, {%8,%9}, {%0,%1,%2,%3};"
                : "+f"(cf[2 * nt][0]), "+f"(cf[2 * nt][1]),
                  "+f"(cf[2 * nt][2]), "+f"(cf[2 * nt][3])
                : "r"(a0), "r"(a1), "r"(a2), "r"(a3), "r"(b0), "r"(b1));
            asm volatile(
                "mma.sync.aligned.m16n8k16.row.col.f32.f16.f16.f32 "
                "{%0,%1,%2,%3}, {%4,%5,%6,%7}, {%8,%9}, {%0,%1,%2,%3};"
                : "+f"(cf[2 * nt + 1][0]), "+f"(cf[2 * nt + 1][1]),
                  "+f"(cf[2 * nt + 1][2]), "+f"(cf[2 * nt + 1][3])
                : "r"(a0), "r"(a1), "r"(a2), "r"(a3), "r"(b2), "r"(b3));
        }
    }

    // epilogue: c layout m16n8 — thread (g=lane>>2, tg=lane&3):
    //   c0,c1 -> row wr0+g,   cols 2tg, 2tg+1
    //   c2,c3 -> row wr0+g+8, cols 2tg, 2tg+1
    int g = lane >> 2, tg = lane & 3;
    int r1 = row0 + wr0 + g;
    int r2 = r1 + 8;
    bool ok1 = r1 < nrows, ok2 = r2 < nrows;
    float s1 = 1.f, s2 = 1.f;
    if (scale) {
        if (ok1) s1 = scale[r1];
        if (ok2) s2 = scale[r2];
    }
#pragma unroll
    for (int t = 0; t < 16; t++) {
        int col = t * 8 + 2 * tg;
        if (ok1) *(__half2*)&out[(size_t)r1 * 128 + col] =
            __floats2half2_rn(cf[t][0] * s1, cf[t][1] * s1);
        if (ok2) *(__half2*)&out[(size_t)r2 * 128 + col] =
            __floats2half2_rn(cf[t][2] * s2, cf[t][3] * s2);
    }
}

// ---------------------------------------------------------------------------
// Aggregate (CSR gather of fp16 rows): warp per node, lane owns 8B (uint2),
// 2-wide edge unroll, fp32 accumulation (best-measured R6 form).
// ---------------------------------------------------------------------------
__device__ __forceinline__ float4 h4f4(uint2 r) {
    __half2 a = *(__half2*)&r.x, b = *(__half2*)&r.y;
    float2 fa = __half22float2(a), fb = __half22float2(b);
    return make_float4(fa.x, fa.y, fb.x, fb.y);
}

__global__ void k_agg(const int* __restrict__ rowptr, const int* __restrict__ csr,
                      const __half* __restrict__ tmp, const float* __restrict__ dinv,
                      const float* __restrict__ edinv, const float* __restrict__ bias,
                      float* __restrict__ out, int n0, int ncnt) {
    int wi = (blockIdx.x * blockDim.x + threadIdx.x) >> 5;
    if (wi >= ncnt) return;
    int w = n0 + wi;
    int lane = threadIdx.x & 31;
    const uint2* t2 = (const uint2*)tmp;

    float4 self = h4f4(t2[(size_t)w * 32 + lane]);
    float se = edinv ? edinv[w] : 1.0f;
    float4 a = make_float4(self.x * se, self.y * se, self.z * se, self.w * se);
    float4 a2 = make_float4(0.f, 0.f, 0.f, 0.f);

    int e   = __ldg(rowptr + w);
    int end = __ldg(rowptr + w + 1);
    if (edinv) {
        for (; e + 1 < end; e += 2) {
            int s0 = __ldg(csr + e);
            int s1 = __ldg(csr + e + 1);
            float e0 = __ldg(edinv + s0), e1 = __ldg(edinv + s1);
            float4 v0 = h4f4(t2[(size_t)s0 * 32 + lane]);
            float4 v1 = h4f4(t2[(size_t)s1 * 32 + lane]);
            a.x = fmaf(v0.x, e0, a.x);  a.y = fmaf(v0.y, e0, a.y);
            a.z = fmaf(v0.z, e0, a.z);  a.w = fmaf(v0.w, e0, a.w);
            a2.x = fmaf(v1.x, e1, a2.x); a2.y = fmaf(v1.y, e1, a2.y);
            a2.z = fmaf(v1.z, e1, a2.z); a2.w = fmaf(v1.w, e1, a2.w);
        }
        if (e < end) {
            int s0 = __ldg(csr + e);
            float e0 = __ldg(edinv + s0);
            float4 v0 = h4f4(t2[(size_t)s0 * 32 + lane]);
            a.x = fmaf(v0.x, e0, a.x); a.y = fmaf(v0.y, e0, a.y);
            a.z = fmaf(v0.z, e0, a.z); a.w = fmaf(v0.w, e0, a.w);
        }
    } else {
        for (; e + 1 < end; e += 2) {
            int s0 = __ldg(csr + e);
            int s1 = __ldg(csr + e + 1);
            float4 v0 = h4f4(t2[(size_t)s0 * 32 + lane]);
            float4 v1 = h4f4(t2[(size_t)s1 * 32 + lane]);
            a.x += v0.x;  a.y += v0.y;  a.z += v0.z;  a.w += v0.w;
            a2.x += v1.x; a2.y += v1.y; a2.z += v1.z; a2.w += v1.w;
        }
        if (e < end) {
            int s0 = __ldg(csr + e);
            float4 v0 = h4f4(t2[(size_t)s0 * 32 + lane]);
            a.x += v0.x; a.y += v0.y; a.z += v0.z; a.w += v0.w;
        }
    }
    a.x += a2.x; a.y += a2.y; a.z += a2.z; a.w += a2.w;

    float sc = dinv[w];
    float4 b = ((const float4*)bias)[lane];
    a.x = fmaxf(fmaf(a.x, sc, b.x), 0.0f);
    a.y = fmaxf(fmaf(a.y, sc, b.y), 0.0f);
    a.z = fmaxf(fmaf(a.z, sc, b.z), 0.0f);
    a.w = fmaxf(fmaf(a.w, sc, b.w), 0.0f);
    ((float4*)out)[(size_t)w * 32 + lane] = a;
}

// ---------------------------------------------------------------------------
// Classifier SIMT GEMM (BN=40), FFMA2 path (fp32-exact logits).
// ---------------------------------------------------------------------------
#define FFMA2(d, a, b) asm("fma.rn.f32x2 %0, %1, %2, %0;" : "+l"(d) : "l"(a), "l"(b))
union U64F2 { unsigned long long u; float2 f; };

template <int BN>
__global__ void k_gemm_cls(const float* __restrict__ A, const float* __restrict__ W,
                           const float* __restrict__ bias,
                           float* __restrict__ out0, int nrows) {
    constexpr int BM = 64;
    constexpr int TX = BN / 4;
    constexpr int TY = BM / 4;
    constexpr int NT = TX * TY;

    extern __shared__ float fsm[];
    float*  Ws = fsm;
    float2* Ad = (float2*)(fsm + 128 * BN);
    float*  As = (float*)(Ad + 128 * BM);

    const int tid  = threadIdx.x;
    const int row0 = blockIdx.x * BM;

    for (int idx = tid; idx < 128 * BN; idx += NT) Ws[idx] = W[idx];
    for (int idx = tid; idx < BM * 128; idx += NT) {
        int r = idx >> 7, k = idx & 127;
        int gr = row0 + r;
        As[r * 129 + k] = (gr < nrows) ? A[(size_t)gr * 128 + k] : 0.0f;
    }
    __syncthreads();
    for (int idx = tid; idx < 128 * BM; idx += NT) {
        int r = idx % BM, k = idx / BM;
        float v = As[r * 129 + k];
        Ad[idx] = make_float2(v, v);
    }
    __syncthreads();

    const int tc = tid % TX, tr = tid / TX;
    unsigned long long acc[4][2];
#pragma unroll
    for (int r = 0; r < 4; r++) { acc[r][0] = 0ull; acc[r][1] = 0ull; }

    const float2* adp = Ad + 4 * tr;
    const float*  wsp = Ws + 4 * tc;

#pragma unroll 8
    for (int k = 0; k < 128; k++) {
        ulonglong2 av0 = *(const ulonglong2*)(adp + (size_t)k * BM);
        ulonglong2 av1 = *(const ulonglong2*)(adp + (size_t)k * BM + 2);
        ulonglong2 wv  = *(const ulonglong2*)(wsp + (size_t)k * BN);
        FFMA2(acc[0][0], av0.x, wv.x); FFMA2(acc[0][1], av0.x, wv.y);
        FFMA2(acc[1][0], av0.y, wv.x); FFMA2(acc[1][1], av0.y, wv.y);
        FFMA2(acc[2][0], av1.x, wv.x); FFMA2(acc[2][1], av1.x, wv.y);
        FFMA2(acc[3][0], av1.y, wv.x); FFMA2(acc[3][1], av1.y, wv.y);
    }

#pragma unroll
    for (int r = 0; r < 4; r++) {
        int row = row0 + 4 * tr + r;
        if (row >= nrows) break;
        U64F2 u0, u1;
        u0.u = acc[r][0];
        u1.u = acc[r][1];
        float4 v = make_float4(u0.f.x + bias[4 * tc + 0], u0.f.y + bias[4 * tc + 1],
                               u1.f.x + bias[4 * tc + 2], u1.f.y + bias[4 * tc + 3]);
        *(float4*)(out0 + (size_t)row * BN + 4 * tc) = v;
    }
}

// ---------------------------------------------------------------------------
extern "C" void kernel_launch(void* const* d_in, const int* in_sizes, int n_in,
                              void* d_out, int out_size) {
    const float* x  = (const float*)d_in[0];
    const int*   ei = (const int*)d_in[1];
    const float* W1 = (const float*)d_in[2];
    const float* b1 = (const float*)d_in[3];
    const float* W2 = (const float*)d_in[4];
    const float* b2 = (const float*)d_in[5];
    const float* W3 = (const float*)d_in[6];
    const float* b3 = (const float*)d_in[7];
    const float* Wc = (const float*)d_in[8];
    const float* bc = (const float*)d_in[9];

    float* out_logits = (float*)d_out;                    // [NN,40]
    float* out_h      = (float*)d_out + (size_t)NN * 40;  // [NN,128]

    __half *tmpA, *tmpB;
    float *h, *dinv;
    int *deg, *rowptr, *cursor, *csr, *bsum;
    cudaGetSymbolAddress((void**)&tmpA,   g_tmpA);
    cudaGetSymbolAddress((void**)&tmpB,   g_tmpB);
    cudaGetSymbolAddress((void**)&h,      g_h);
    cudaGetSymbolAddress((void**)&dinv,   g_dinv);
    cudaGetSymbolAddress((void**)&deg,    g_deg);
    cudaGetSymbolAddress((void**)&rowptr, g_rowptr);
    cudaGetSymbolAddress((void**)&cursor, g_cursor);
    cudaGetSymbolAddress((void**)&csr,    g_csr);
    cudaGetSymbolAddress((void**)&bsum,   g_bsum);

    const int SM40 = 128 * 40 * 4 + 128 * 64 * 8 + 64 * 129 * 4;
    cudaFuncSetAttribute(k_gemm_mma, cudaFuncAttributeMaxDynamicSharedMemorySize, MMA_SMEM_BYTES);
    cudaFuncSetAttribute(k_gemm_cls<40>, cudaFuncAttributeMaxDynamicSharedMemorySize, SM40);

    cudaStream_t S = g_ctx.s;
    cudaEvent_t* E = g_ctx.e;

    // fork side stream off the capture (main) stream
    cudaEventRecord(E[0], 0);
    cudaStreamWaitEvent(S, E[0], 0);

    // ---- side stream: normalization + CSR build (5 launches, hidden) ----
    k_deg_init<<<(NN + 255) / 256, 256, 0, S>>>(deg);
    k_deg_count<<<(NE + 255) / 256, 256, 0, S>>>(ei, deg);
    k_scan1<<<NB, 512, 0, S>>>(deg, rowptr, bsum, dinv);
    k_scan3<<<NB, 512, 0, S>>>(rowptr, bsum, cursor);
    k_fill<<<(NE + 255) / 256, 256, 0, S>>>(ei, cursor, csr);
    cudaEventRecord(E[1], S);   // CSR + dinv ready

    // ---- main: layer 1 GEMM -> tmpA (unscaled; no dinv dependency) ----
    k_gemm_mma<<<(NN + 127) / 128, 256, MMA_SMEM_BYTES>>>(x, W1, nullptr, tmpA, NN);

    // agg layer 1 reads tmpA (dinv[src] per edge), writes h
    cudaStreamWaitEvent(0, E[1], 0);
    k_agg<<<HA / 8, 256>>>(rowptr, csr, tmpA, dinv, dinv, b1, h, 0, HA);
    cudaEventRecord(E[2], 0);   // h rows [0,HA) ready
    k_agg<<<HB / 8, 256>>>(rowptr, csr, tmpA, dinv, dinv, b1, h, HA, HB);

    // side: GEMM2-A (reads h[0:HA), writes tmpB) overlaps agg1-B (reads tmpA)
    cudaStreamWaitEvent(S, E[2], 0);
    k_gemm_mma<<<HA / 128, 256, MMA_SMEM_BYTES, S>>>(h, W2, dinv, tmpB, HA);
    cudaEventRecord(E[3], S);
    // main: GEMM2-B
    k_gemm_mma<<<(HB + 127) / 128, 256, MMA_SMEM_BYTES>>>(h + (size_t)HA * 128, W2,
                                                          dinv + HA, tmpB + (size_t)HA * 128, HB);
    cudaStreamWaitEvent(0, E[3], 0);
    // agg layer 2 reads tmpB, writes h
    k_agg<<<HA / 8, 256>>>(rowptr, csr, tmpB, dinv, nullptr, b2, h, 0, HA);
    cudaEventRecord(E[4], 0);
    k_agg<<<HB / 8, 256>>>(rowptr, csr, tmpB, dinv, nullptr, b2, h, HA, HB);

    // side: GEMM3-A (reads h[0:HA), writes tmpA) overlaps agg2-B (reads tmpB)
    cudaStreamWaitEvent(S, E[4], 0);
    k_gemm_mma<<<HA / 128, 256, MMA_SMEM_BYTES, S>>>(h, W3, dinv, tmpA, HA);
    cudaEventRecord(E[5], S);
    // main: GEMM3-B
    k_gemm_mma<<<(HB + 127) / 128, 256, MMA_SMEM_BYTES>>>(h + (size_t)HA * 128, W3,
                                                          dinv + HA, tmpA + (size_t)HA * 128, HB);
    cudaStreamWaitEvent(0, E[5], 0);
    // agg layer 3 reads tmpA, writes out_h
    k_agg<<<HA / 8, 256>>>(rowptr, csr, tmpA, dinv, nullptr, b3, out_h, 0, HA);
    cudaEventRecord(E[6], 0);
    k_agg<<<HB / 8, 256>>>(rowptr, csr, tmpA, dinv, nullptr, b3, out_h, HA, HB);

    // side: classifier-A (reads out_h[0:HA)) overlaps agg3-B (writes out_h[HA:))
    cudaStreamWaitEvent(S, E[6], 0);
    k_gemm_cls<40><<<HA / 64, 160, SM40, S>>>(out_h, Wc, bc, out_logits, HA);
    cudaEventRecord(E[7], S);
    // main: classifier-B
    k_gemm_cls<40><<<(HB + 63) / 64, 160, SM40>>>(out_h + (size_t)HA * 128, Wc, bc,
                                                  out_logits + (size_t)HA * 40, HB);
    // join side stream back into main before capture ends
    cudaStreamWaitEvent(0, E[7], 0);
}